// round 1
// baseline (speedup 1.0000x reference)
#include <cuda_runtime.h>
#include <cuda_bf16.h>
#include <math.h>

// ---------------- problem constants ----------------
#define BB   32
#define CC   256
#define HH   56
#define OHW  28
#define QQ   784      // 28*28 spatial
#define PP   784      // correlation channels
#define NTOT (BB*QQ)  // 25088

// ---------------- scratch (static device arrays; no allocation allowed) ----
__device__ float g_f1r[(size_t)BB*CC*QQ];        // (b,c,q) resized feature1
__device__ float g_f2r[(size_t)BB*CC*QQ];        // (b,c,q) resized feature2
__device__ float g_mp [BB*QQ];                   // pooled mask (b,q)
__device__ float g_corr [(size_t)BB*PP*QQ];      // (b,p,q)
__device__ float g_corrp[(size_t)BB*PP*QQ];      // maxpool3 of corr
__device__ float g_norm2[BB*QQ];
__device__ float g_y   [(size_t)BB*512*QQ];      // concat pre-BN
__device__ float g_y2a [(size_t)BB*192*QQ];
__device__ float g_y3a [(size_t)BB*32*QQ];
__device__ float g_col2[(size_t)1728*NTOT];      // im2col for 3x3 conv
__device__ float g_col3[(size_t)800*NTOT];       // im2col for 5x5 conv
__device__ float g_W1t [784*128];
__device__ float g_W2at[784*192];
__device__ float g_W3at[784*32];
__device__ float g_W4t [784*64];
__device__ float g_W2bt[1728*256];
__device__ float g_W3bt[800*64];
__device__ float g_mean[512];
__device__ float g_inv [512];

// ---------------- bilinear resize (align_corners) for both features -------
__global__ void resize2_kernel(const float* __restrict__ f1,
                               const float* __restrict__ f2)
{
    int idx = blockIdx.x * blockDim.x + threadIdx.x;
    const int TOT = BB * CC * QQ;
    if (idx >= 2 * TOT) return;
    const float* src = f1;
    float* dst = g_f1r;
    int i = idx;
    if (i >= TOT) { i -= TOT; src = f2; dst = g_f2r; }
    int q = i % QQ;
    int r = i / QQ;               // b*C + c
    int oy = q / OHW, ox = q % OHW;
    const float s = 55.0f / 27.0f;
    float fy = oy * s, fx = ox * s;
    int y0 = (int)fy; float wy = fy - (float)y0; int y1 = min(y0 + 1, HH - 1);
    int x0 = (int)fx; float wx = fx - (float)x0; int x1 = min(x0 + 1, HH - 1);
    const float* p = src + (size_t)r * HH * HH;
    float v00 = p[y0 * HH + x0], v01 = p[y0 * HH + x1];
    float v10 = p[y1 * HH + x0], v11 = p[y1 * HH + x1];
    float r0 = v00 * (1.f - wy) + v10 * wy;
    float r1 = v01 * (1.f - wy) + v11 * wy;
    dst[i] = r0 * (1.f - wx) + r1 * wx;
}

// ---------------- 2x2 stride-2 maxpool of mask ----------------------------
__global__ void maskpool_kernel(const float* __restrict__ m)
{
    int idx = blockIdx.x * blockDim.x + threadIdx.x;
    if (idx >= BB * QQ) return;
    int b = idx / QQ, q = idx % QQ;
    int oy = q / OHW, ox = q % OHW;
    const float* p = m + (size_t)b * HH * HH;
    int y = oy * 2, x = ox * 2;
    float v = fmaxf(fmaxf(p[y*HH+x], p[y*HH+x+1]),
                    fmaxf(p[(y+1)*HH+x], p[(y+1)*HH+x+1]));
    g_mp[idx] = v;
}

// ---------------- generic weight transpose: (M,K) -> (K,M) ---------------
__global__ void transpose_kernel(const float* __restrict__ in,
                                 float* __restrict__ out, int M, int K)
{
    int idx = blockIdx.x * blockDim.x + threadIdx.x;
    if (idx >= M * K) return;
    int m = idx / K, k = idx - m * K;
    out[k * M + m] = in[idx];
}

// ---------------- tiled fp32 GEMM: O[m,n] = sum_k A[k,m]*B[k,n] -----------
// A, B both K-major.  Optional batch (blockIdx.z), bias[m], relu.
__global__ __launch_bounds__(256) void gemm_kt(
    const float* __restrict__ A, size_t sA, int lda,
    const float* __restrict__ Bm, size_t sB, int ldb,
    float* __restrict__ O, size_t sO, int ldo,
    const float* __restrict__ bias,
    int M, int N, int K, int relu)
{
    __shared__ float As[8][128];
    __shared__ float Bs[8][128];
    int bz = blockIdx.z;
    A  += (size_t)bz * sA;
    Bm += (size_t)bz * sB;
    O  += (size_t)bz * sO;
    int m0 = blockIdx.y * 128, n0 = blockIdx.x * 128;
    int tid = threadIdx.x;
    int tx = tid & 15, ty = tid >> 4;

    float acc[8][8];
#pragma unroll
    for (int i = 0; i < 8; i++)
#pragma unroll
        for (int j = 0; j < 8; j++) acc[i][j] = 0.f;

    for (int k0 = 0; k0 < K; k0 += 8) {
#pragma unroll
        for (int t = 0; t < 4; t++) {
            int idx = tid + t * 256;
            int kk = idx >> 7, col = idx & 127;
            int m = m0 + col;
            As[kk][col] = (m < M) ? A[(size_t)(k0 + kk) * lda + m] : 0.f;
            int n = n0 + col;
            Bs[kk][col] = (n < N) ? Bm[(size_t)(k0 + kk) * ldb + n] : 0.f;
        }
        __syncthreads();
#pragma unroll
        for (int kk = 0; kk < 8; kk++) {
            float4 a0 = *(const float4*)&As[kk][ty * 8];
            float4 a1 = *(const float4*)&As[kk][ty * 8 + 4];
            float4 b0 = *(const float4*)&Bs[kk][tx * 8];
            float4 b1 = *(const float4*)&Bs[kk][tx * 8 + 4];
            float ar[8] = {a0.x,a0.y,a0.z,a0.w,a1.x,a1.y,a1.z,a1.w};
            float br[8] = {b0.x,b0.y,b0.z,b0.w,b1.x,b1.y,b1.z,b1.w};
#pragma unroll
            for (int i = 0; i < 8; i++)
#pragma unroll
                for (int j = 0; j < 8; j++)
                    acc[i][j] = fmaf(ar[i], br[j], acc[i][j]);
        }
        __syncthreads();
    }

#pragma unroll
    for (int i = 0; i < 8; i++) {
        int m = m0 + ty * 8 + i;
        if (m >= M) continue;
        float bv = bias ? bias[m] : 0.f;
#pragma unroll
        for (int j = 0; j < 8; j++) {
            int n = n0 + tx * 8 + j;
            if (n >= N) continue;
            float v = acc[i][j] + bv;
            if (relu) v = fmaxf(v, 0.f);
            O[(size_t)m * ldo + n] = v;
        }
    }
}

// ---------------- deterministic column L2-norm^2 over p -------------------
__global__ void colnorm_kernel()
{
    int idx = blockIdx.x * blockDim.x + threadIdx.x;
    if (idx >= BB * QQ) return;
    int b = idx / QQ, q = idx % QQ;
    const float* p = g_corr + (size_t)b * PP * QQ + q;
    float s = 0.f;
#pragma unroll 4
    for (int pp = 0; pp < PP; pp++) {
        float v = p[(size_t)pp * QQ];
        s = fmaf(v, v, s);
    }
    g_norm2[idx] = s;
}

// ---------------- corr *= mask/norm ---------------------------------------
__global__ void scalecorr_kernel()
{
    int idx = blockIdx.x * blockDim.x + threadIdx.x;
    if (idx >= BB * PP * QQ) return;
    int b = idx / (PP * QQ);
    int q = idx % QQ;
    int bq = b * QQ + q;
    float sc = g_mp[bq] * rsqrtf(g_norm2[bq]);
    g_corr[idx] *= sc;
}

// ---------------- 3x3 stride-1 pad-1 maxpool over (h,w) -------------------
__global__ void mp3_kernel()
{
    int idx = blockIdx.x * blockDim.x + threadIdx.x;
    if (idx >= BB * PP * QQ) return;
    int q = idx % QQ;
    int oy = q / OHW, ox = q % OHW;
    const float* base = g_corr + (size_t)(idx - q);
    float mx = -1e30f;
#pragma unroll
    for (int dy = -1; dy <= 1; dy++) {
        int y = oy + dy;
        if ((unsigned)y >= OHW) continue;
#pragma unroll
        for (int dx = -1; dx <= 1; dx++) {
            int x = ox + dx;
            if ((unsigned)x >= OHW) continue;
            mx = fmaxf(mx, base[y * OHW + x]);
        }
    }
    g_corrp[idx] = mx;
}

// ---------------- im2col (3x3 pad1, IC=192) from g_y2a --------------------
__global__ void im2col3_kernel()
{
    int idx = blockIdx.x * blockDim.x + threadIdx.x;
    if (idx >= 1728 * NTOT) return;
    int n = idx % NTOT;
    int krow = idx / NTOT;
    int ic = krow / 9, kk = krow - ic * 9;
    int ky = kk / 3, kx = kk - ky * 3;
    int b = n / QQ, q = n - b * QQ;
    int oy = q / OHW, ox = q - oy * OHW;
    int iy = oy + ky - 1, ix = ox + kx - 1;
    float v = 0.f;
    if ((unsigned)iy < OHW && (unsigned)ix < OHW)
        v = g_y2a[((size_t)(b * 192 + ic)) * QQ + iy * OHW + ix];
    g_col2[idx] = v;
}

// ---------------- im2col (5x5 pad2, IC=32) from g_y3a ---------------------
__global__ void im2col5_kernel()
{
    int idx = blockIdx.x * blockDim.x + threadIdx.x;
    if (idx >= 800 * NTOT) return;
    int n = idx % NTOT;
    int krow = idx / NTOT;
    int ic = krow / 25, kk = krow - ic * 25;
    int ky = kk / 5, kx = kk - ky * 5;
    int b = n / QQ, q = n - b * QQ;
    int oy = q / OHW, ox = q - oy * OHW;
    int iy = oy + ky - 2, ix = ox + kx - 2;
    float v = 0.f;
    if ((unsigned)iy < OHW && (unsigned)ix < OHW)
        v = g_y3a[((size_t)(b * 32 + ic)) * QQ + iy * OHW + ix];
    g_col3[idx] = v;
}

// ---------------- BatchNorm statistics (fp64 accumulate) ------------------
__global__ void bnstats_kernel()
{
    int c = blockIdx.x;           // 512 blocks
    int t = threadIdx.x;          // 256 threads
    double s = 0.0, s2 = 0.0;
    for (int e = t; e < NTOT; e += 256) {
        int b = e / QQ, q = e - b * QQ;
        float v = g_y[((size_t)b * 512 + c) * QQ + q];
        s += (double)v;
        s2 += (double)v * (double)v;
    }
    __shared__ double sh[256], sh2[256];
    sh[t] = s; sh2[t] = s2;
    __syncthreads();
    for (int off = 128; off; off >>= 1) {
        if (t < off) { sh[t] += sh[t + off]; sh2[t] += sh2[t + off]; }
        __syncthreads();
    }
    if (t == 0) {
        double mu = sh[0] / (double)NTOT;
        double var = sh2[0] / (double)NTOT - mu * mu;
        g_mean[c] = (float)mu;
        g_inv[c]  = (float)(1.0 / sqrt(var + 1e-5));
    }
}

__global__ void bnapply_kernel(const float* __restrict__ gamma,
                               const float* __restrict__ beta,
                               float* __restrict__ out)
{
    int idx = blockIdx.x * blockDim.x + threadIdx.x;
    if (idx >= BB * 512 * QQ) return;
    int c = (idx / QQ) & 511;
    out[idx] = gamma[c] * (g_y[idx] - g_mean[c]) * g_inv[c] + beta[c];
}

// ---------------- host side ------------------------------------------------
static float* symaddr(const void* sym)
{
    void* p = nullptr;
    cudaGetSymbolAddress(&p, sym);
    return (float*)p;
}

extern "C" void kernel_launch(void* const* d_in, const int* in_sizes, int n_in,
                              void* d_out, int out_size)
{
    const float* f1    = (const float*)d_in[0];
    const float* f2    = (const float*)d_in[1];
    const float* mask  = (const float*)d_in[2];
    const float* W1    = (const float*)d_in[3];
    const float* b1    = (const float*)d_in[4];
    const float* W2a   = (const float*)d_in[5];
    const float* b2a   = (const float*)d_in[6];
    const float* W2b   = (const float*)d_in[7];
    const float* b2b   = (const float*)d_in[8];
    const float* W3a   = (const float*)d_in[9];
    const float* b3a   = (const float*)d_in[10];
    const float* W3b   = (const float*)d_in[11];
    const float* b3b   = (const float*)d_in[12];
    const float* W4    = (const float*)d_in[13];
    const float* b4    = (const float*)d_in[14];
    const float* gamma = (const float*)d_in[15];
    const float* beta  = (const float*)d_in[16];
    float* out = (float*)d_out;

    float* p_f1r   = symaddr(g_f1r);
    float* p_f2r   = symaddr(g_f2r);
    float* p_corr  = symaddr(g_corr);
    float* p_corrp = symaddr(g_corrp);
    float* p_y     = symaddr(g_y);
    float* p_y2a   = symaddr(g_y2a);
    float* p_y3a   = symaddr(g_y3a);
    float* p_col2  = symaddr(g_col2);
    float* p_col3  = symaddr(g_col3);
    float* p_W1t   = symaddr(g_W1t);
    float* p_W2at  = symaddr(g_W2at);
    float* p_W3at  = symaddr(g_W3at);
    float* p_W4t   = symaddr(g_W4t);
    float* p_W2bt  = symaddr(g_W2bt);
    float* p_W3bt  = symaddr(g_W3bt);

    const int T = 256;
    // 1) resize both features, pool mask
    resize2_kernel<<<(2*BB*CC*QQ + T-1)/T, T>>>(f1, f2);
    maskpool_kernel<<<(BB*QQ + T-1)/T, T>>>(mask);

    // 2) transpose weights to K-major
    transpose_kernel<<<(128*784 + T-1)/T, T>>>(W1,  p_W1t, 128, 784);
    transpose_kernel<<<(192*784 + T-1)/T, T>>>(W2a, p_W2at, 192, 784);
    transpose_kernel<<<(32*784  + T-1)/T, T>>>(W3a, p_W3at, 32, 784);
    transpose_kernel<<<(64*784  + T-1)/T, T>>>(W4,  p_W4t, 64, 784);
    transpose_kernel<<<(256*1728+ T-1)/T, T>>>(W2b, p_W2bt, 256, 1728);
    transpose_kernel<<<(64*800  + T-1)/T, T>>>(W3b, p_W3bt, 64, 800);

    // 3) cost volume: corr[b,p,q] = relu(sum_c f1r[b,c,p] * f2r[b,c,q])
    {
        dim3 g((QQ+127)/128, (PP+127)/128, BB);
        gemm_kt<<<g, 256>>>(p_f1r, (size_t)CC*QQ, QQ,
                            p_f2r, (size_t)CC*QQ, QQ,
                            p_corr, (size_t)PP*QQ, QQ,
                            nullptr, PP, QQ, CC, 1);
    }
    // 4) L2 norm over p, then scale by mask/norm
    colnorm_kernel<<<(BB*QQ + T-1)/T, T>>>();
    scalecorr_kernel<<<(BB*PP*QQ + T-1)/T, T>>>();

    // 5) 3x3 maxpool of normalized corr (for branch 4)
    mp3_kernel<<<(BB*PP*QQ + T-1)/T, T>>>();

    // 6) 1x1 conv branches (batched GEMM over b)
    {
        dim3 g((QQ+127)/128, 1, BB);
        // y1: 784 -> 128, into y channels [0,128)
        gemm_kt<<<g, 256>>>(p_W1t, 0, 128,
                            p_corr, (size_t)PP*QQ, QQ,
                            p_y, (size_t)512*QQ, QQ,
                            b1, 128, QQ, PP, 1);
        // y2a: 784 -> 192
        dim3 g2((QQ+127)/128, 2, BB);
        gemm_kt<<<g2, 256>>>(p_W2at, 0, 192,
                             p_corr, (size_t)PP*QQ, QQ,
                             p_y2a, (size_t)192*QQ, QQ,
                             b2a, 192, QQ, PP, 1);
        // y3a: 784 -> 32
        gemm_kt<<<g, 256>>>(p_W3at, 0, 32,
                            p_corr, (size_t)PP*QQ, QQ,
                            p_y3a, (size_t)32*QQ, QQ,
                            b3a, 32, QQ, PP, 1);
        // y4: maxpooled corr 784 -> 64, into y channels [448,512)
        gemm_kt<<<g, 256>>>(p_W4t, 0, 64,
                            p_corrp, (size_t)PP*QQ, QQ,
                            p_y + (size_t)448*QQ, (size_t)512*QQ, QQ,
                            b4, 64, QQ, PP, 1);
    }

    // 7) 3x3 conv 192->256 via im2col + GEMM, into y channels [128,384)
    im2col3_kernel<<<(1728*NTOT + T-1)/T, T>>>();
    {
        dim3 g((QQ+127)/128, 2, BB);
        gemm_kt<<<g, 256>>>(p_W2bt, 0, 256,
                            p_col2, (size_t)QQ, NTOT,
                            p_y + (size_t)128*QQ, (size_t)512*QQ, QQ,
                            b2b, 256, QQ, 1728, 1);
    }

    // 8) 5x5 conv 32->64 via im2col + GEMM, into y channels [384,448)
    im2col5_kernel<<<(800*NTOT + T-1)/T, T>>>();
    {
        dim3 g((QQ+127)/128, 1, BB);
        gemm_kt<<<g, 256>>>(p_W3bt, 0, 64,
                            p_col3, (size_t)QQ, NTOT,
                            p_y + (size_t)384*QQ, (size_t)512*QQ, QQ,
                            b3b, 64, QQ, 800, 1);
    }

    // 9) BatchNorm (training-mode batch stats) -> d_out
    bnstats_kernel<<<512, 256>>>();
    bnapply_kernel<<<(BB*512*QQ + T-1)/T, T>>>(gamma, beta, out);
}

// round 10
// speedup vs baseline: 1.0741x; 1.0741x over previous
#include <cuda_runtime.h>
#include <cuda_bf16.h>
#include <cstdint>
#include <math.h>

// ---------------- problem constants ----------------
#define BB   32
#define CC   256
#define HH   56
#define OHW  28
#define QQ   784
#define PP   784
#define NTOT (BB*QQ)   // 25088

// ---------------- scratch (static device arrays) ---------------------------
__device__ float g_f1r[(size_t)BB*CC*QQ];
__device__ float g_f2r[(size_t)BB*CC*QQ];
__device__ float g_mp [NTOT];
__device__ float g_cs [NTOT];                 // mask * rsqrt(norm2)
__device__ float g_corr [(size_t)PP*NTOT];    // (p, n)
__device__ float g_corrp[(size_t)PP*NTOT];    // scaled+maxpooled (p, n)
__device__ float g_y   [(size_t)512*NTOT];    // (c, n) concat pre-BN
__device__ float g_y2a [(size_t)192*NTOT];
__device__ float g_y3a [(size_t)32*NTOT];
__device__ float g_col2[(size_t)1728*NTOT];
__device__ float g_col3[(size_t)800*NTOT];
__device__ float g_W1t [784*128];
__device__ float g_W2at[784*192];
__device__ float g_W3at[784*32];
__device__ float g_W4t [784*64];
__device__ float g_W2bt[1728*256];
__device__ float g_W3bt[800*64];
__device__ float g_mean[512];
__device__ float g_inv [512];

// ====================== warp-MMA GEMM (mma.sync bf16) ======================
// O[m,n] = relu( sum_k A[k,m]*B[k,n]*(cs?cs[n]:1) + bias[m] )
// A,B K-major fp32 in gmem. Inside: split each fp32 into bf16 hi+lo and
// compute Ah*Bh + Ah*Bl + Al*Bh with fp32 accumulators (rel err ~1e-5).
#define TILE 128
#define KC   32
#define RSB  80                   // smem row stride bytes (32 bf16 + 8 pad)
#define ASZ  (128*RSB)            // 10240 B per matrix tile
#define STAGE (4*ASZ)             // Ah, Al, Bh, Bl
#define GEMM_SMEM (2*STAGE)       // double buffered = 81920 B

__device__ __forceinline__ uint32_t smem_u32(const void* p) {
    return (uint32_t)__cvta_generic_to_shared((void*)p);
}

__device__ __forceinline__ void cvt_pack(float v0, float v1,
                                         uint32_t& hi, uint32_t& lo) {
    __nv_bfloat16 h0 = __float2bfloat16(v0);
    __nv_bfloat16 h1 = __float2bfloat16(v1);
    __nv_bfloat16 l0 = __float2bfloat16(v0 - __bfloat162float(h0));
    __nv_bfloat16 l1 = __float2bfloat16(v1 - __bfloat162float(h1));
    hi = (uint32_t)__bfloat16_as_ushort(h0) | ((uint32_t)__bfloat16_as_ushort(h1) << 16);
    lo = (uint32_t)__bfloat16_as_ushort(l0) | ((uint32_t)__bfloat16_as_ushort(l1) << 16);
}

__device__ __forceinline__ void ldm_x4(uint32_t* r, uint32_t a) {
    asm volatile("ldmatrix.sync.aligned.m8n8.x4.shared.b16 {%0,%1,%2,%3}, [%4];"
                 : "=r"(r[0]), "=r"(r[1]), "=r"(r[2]), "=r"(r[3]) : "r"(a));
}

__device__ __forceinline__ void mma_bf16(float* c, const uint32_t* a,
                                         uint32_t b0, uint32_t b1) {
    asm volatile(
        "mma.sync.aligned.m16n8k16.row.col.f32.bf16.bf16.f32 "
        "{%0,%1,%2,%3}, {%4,%5,%6,%7}, {%8,%9}, {%0,%1,%2,%3};"
        : "+f"(c[0]), "+f"(c[1]), "+f"(c[2]), "+f"(c[3])
        : "r"(a[0]), "r"(a[1]), "r"(a[2]), "r"(a[3]), "r"(b0), "r"(b1));
}

// Fill one stage: A tile [m][k] and B^T tile [n][k], hi/lo bf16, K-bounds zeroed.
__device__ void fill_stage(char* st,
    const float* __restrict__ A, int lda, int m0, int M,
    const float* __restrict__ B, int ldb, int n0, int N,
    const float* __restrict__ cs, int k0, int K)
{
    int tid = threadIdx.x;
#pragma unroll
    for (int i = 0; i < 8; i++) {
        int idx = (i << 8) + tid;          // 0..2047
        int r   = idx & 127;               // row (m or n) — coalesced
        int kp  = idx >> 7;                // k-pair 0..15
        int k   = k0 + (kp << 1);
        uint32_t off = (uint32_t)(r * RSB + (kp << 2));
        // ---- A (rows = m)
        float a0 = 0.f, a1 = 0.f;
        int gm = m0 + r;
        if (gm < M) {
            if (k     < K) a0 = A[(size_t)k * lda + gm];
            if (k + 1 < K) a1 = A[(size_t)(k + 1) * lda + gm];
        }
        uint32_t hi, lo;
        cvt_pack(a0, a1, hi, lo);
        *(uint32_t*)(st + off)           = hi;
        *(uint32_t*)(st + ASZ + off)     = lo;
        // ---- B (rows = n), optionally scaled by cs[n]
        float b0 = 0.f, b1 = 0.f;
        int gn = n0 + r;
        if (gn < N) {
            float sc = cs ? cs[gn] : 1.f;
            if (k     < K) b0 = B[(size_t)k * ldb + gn] * sc;
            if (k + 1 < K) b1 = B[(size_t)(k + 1) * ldb + gn] * sc;
        }
        cvt_pack(b0, b1, hi, lo);
        *(uint32_t*)(st + 2 * ASZ + off) = hi;
        *(uint32_t*)(st + 3 * ASZ + off) = lo;
    }
}

__global__ __launch_bounds__(256, 2)
void gemm_tc(const float* __restrict__ A, size_t sA, int lda,
             const float* __restrict__ B, size_t sB, int ldb,
             float* __restrict__ O, size_t sO, int ldo,
             const float* __restrict__ bias,
             const float* __restrict__ cs,
             int M, int N, int K)
{
    extern __shared__ char smem[];
    int bz = blockIdx.z;
    A += (size_t)bz * sA; B += (size_t)bz * sB; O += (size_t)bz * sO;
    int m0 = blockIdx.y * TILE, n0 = blockIdx.x * TILE;
    int tid = threadIdx.x, wid = tid >> 5, lane = tid & 31;

    int wm = (wid >> 1) << 5;     // warp m offset: 0,32,64,96
    int wn = (wid & 1) << 6;      // warp n offset: 0,64
    int quad = lane >> 3, li = lane & 7;
    int aRow = (quad & 1) * 8 + li;       // ldmatrix A row-in-16
    int aK   = (quad >> 1) * 8;           // ldmatrix A k-offset
    int bRow = (quad >> 1) * 8 + li;      // ldmatrix B n-row-in-16
    int bK   = (quad & 1) * 8;            // ldmatrix B k-offset

    float acc[2][8][4];
#pragma unroll
    for (int a = 0; a < 2; a++)
#pragma unroll
        for (int b = 0; b < 8; b++)
#pragma unroll
            for (int c = 0; c < 4; c++) acc[a][b][c] = 0.f;

    int nch = (K + KC - 1) / KC;
    fill_stage(smem, A, lda, m0, M, B, ldb, n0, N, cs, 0, K);
    __syncthreads();

    for (int ic = 0; ic < nch; ic++) {
        char* st = smem + (ic & 1) * STAGE;
        if (ic + 1 < nch)
            fill_stage(smem + ((ic + 1) & 1) * STAGE,
                       A, lda, m0, M, B, ldb, n0, N, cs, (ic + 1) * KC, K);

        uint32_t Ah = smem_u32(st);
        uint32_t Al = Ah + ASZ, Bh = Ah + 2 * ASZ, Bl = Ah + 3 * ASZ;
#pragma unroll
        for (int ks = 0; ks < 2; ks++) {
            uint32_t ah[2][4], al[2][4];
#pragma unroll
            for (int mf = 0; mf < 2; mf++) {
                uint32_t ra = (uint32_t)((wm + mf * 16 + aRow) * RSB +
                                         (ks * 16 + aK) * 2);
                ldm_x4(ah[mf], Ah + ra);
                ldm_x4(al[mf], Al + ra);
            }
#pragma unroll
            for (int p = 0; p < 4; p++) {
                uint32_t rb = (uint32_t)((wn + p * 16 + bRow) * RSB +
                                         (ks * 16 + bK) * 2);
                uint32_t bh[4], bl[4];
                ldm_x4(bh, Bh + rb);
                ldm_x4(bl, Bl + rb);
#pragma unroll
                for (int mf = 0; mf < 2; mf++) {
                    mma_bf16(acc[mf][2 * p],     ah[mf], bh[0], bh[1]);
                    mma_bf16(acc[mf][2 * p],     ah[mf], bl[0], bl[1]);
                    mma_bf16(acc[mf][2 * p],     al[mf], bh[0], bh[1]);
                    mma_bf16(acc[mf][2 * p + 1], ah[mf], bh[2], bh[3]);
                    mma_bf16(acc[mf][2 * p + 1], ah[mf], bl[2], bl[3]);
                    mma_bf16(acc[mf][2 * p + 1], al[mf], bh[2], bh[3]);
                }
            }
        }
        __syncthreads();
    }

    // epilogue: bias + relu, fragment scatter
#pragma unroll
    for (int mf = 0; mf < 2; mf++) {
        int mb = m0 + wm + mf * 16 + (lane >> 2);
#pragma unroll
        for (int half = 0; half < 2; half++) {
            int m = mb + half * 8;
            if (m >= M) continue;
            float bv = bias ? bias[m] : 0.f;
            float* orow = O + (size_t)m * ldo;
#pragma unroll
            for (int nf = 0; nf < 8; nf++) {
                int n = n0 + wn + nf * 8 + ((lane & 3) << 1);
                float v0 = fmaxf(acc[mf][nf][half * 2 + 0] + bv, 0.f);
                float v1 = fmaxf(acc[mf][nf][half * 2 + 1] + bv, 0.f);
                if (n < N)     orow[n]     = v0;
                if (n + 1 < N) orow[n + 1] = v1;
            }
        }
    }
}

// ====================== elementwise kernels ================================
__global__ void resize2_kernel(const float* __restrict__ f1,
                               const float* __restrict__ f2)
{
    int idx = blockIdx.x * blockDim.x + threadIdx.x;
    const int TOT = BB * CC * QQ;
    if (idx >= 2 * TOT) return;
    const float* src = f1; float* dst = g_f1r;
    int i = idx;
    if (i >= TOT) { i -= TOT; src = f2; dst = g_f2r; }
    int q = i % QQ;
    int r = i / QQ;
    int oy = q / OHW, ox = q % OHW;
    const float s = 55.0f / 27.0f;
    float fy = oy * s, fx = ox * s;
    int y0 = (int)fy; float wy = fy - (float)y0; int y1 = min(y0 + 1, HH - 1);
    int x0 = (int)fx; float wx = fx - (float)x0; int x1 = min(x0 + 1, HH - 1);
    const float* p = src + (size_t)r * HH * HH;
    float v00 = p[y0 * HH + x0], v01 = p[y0 * HH + x1];
    float v10 = p[y1 * HH + x0], v11 = p[y1 * HH + x1];
    float r0 = v00 * (1.f - wy) + v10 * wy;
    float r1 = v01 * (1.f - wy) + v11 * wy;
    dst[i] = r0 * (1.f - wx) + r1 * wx;
}

__global__ void maskpool_kernel(const float* __restrict__ m)
{
    int idx = blockIdx.x * blockDim.x + threadIdx.x;
    if (idx >= NTOT) return;
    int b = idx / QQ, q = idx % QQ;
    int oy = q / OHW, ox = q % OHW;
    const float* p = m + (size_t)b * HH * HH;
    int y = oy * 2, x = ox * 2;
    g_mp[idx] = fmaxf(fmaxf(p[y*HH+x], p[y*HH+x+1]),
                      fmaxf(p[(y+1)*HH+x], p[(y+1)*HH+x+1]));
}

__global__ void transpose_kernel(const float* __restrict__ in,
                                 float* __restrict__ out, int M, int K)
{
    int idx = blockIdx.x * blockDim.x + threadIdx.x;
    if (idx >= M * K) return;
    int m = idx / K, k = idx - m * K;
    out[k * M + m] = in[idx];
}

// cs[n] = mp[n] * rsqrt(sum_p corr[p,n]^2)
__global__ void colnorm_kernel()
{
    int n = blockIdx.x * blockDim.x + threadIdx.x;
    if (n >= NTOT) return;
    const float* p = g_corr + n;
    float s = 0.f;
#pragma unroll 8
    for (int pp = 0; pp < PP; pp++) {
        float v = p[(size_t)pp * NTOT];
        s = fmaf(v, v, s);
    }
    g_cs[n] = g_mp[n] * rsqrtf(s);
}

// corrp[p,n] = max over 3x3 spatial nbhd of corr[p,.]*cs[.]
__global__ void mp3_kernel()
{
    int idx = blockIdx.x * blockDim.x + threadIdx.x;
    if (idx >= PP * NTOT) return;
    int p = idx / NTOT;
    int n = idx - p * NTOT;
    int b = n / QQ;
    int q = n - b * QQ;
    int oy = q / OHW, ox = q - oy * OHW;
    const float* base = g_corr + (size_t)p * NTOT + b * QQ;
    const float* csb  = g_cs + b * QQ;
    float mx = -1e30f;
#pragma unroll
    for (int dy = -1; dy <= 1; dy++) {
        int y = oy + dy;
        if ((unsigned)y >= OHW) continue;
#pragma unroll
        for (int dx = -1; dx <= 1; dx++) {
            int x = ox + dx;
            if ((unsigned)x >= OHW) continue;
            int qq = y * OHW + x;
            mx = fmaxf(mx, base[qq] * csb[qq]);
        }
    }
    g_corrp[idx] = mx;
}

__global__ void im2col3_kernel()
{
    size_t idx = (size_t)blockIdx.x * blockDim.x + threadIdx.x;
    if (idx >= (size_t)1728 * NTOT) return;
    int n = (int)(idx % NTOT);
    int krow = (int)(idx / NTOT);
    int ic = krow / 9, kk = krow - ic * 9;
    int ky = kk / 3, kx = kk - ky * 3;
    int b = n / QQ, q = n - b * QQ;
    int oy = q / OHW, ox = q - oy * OHW;
    int iy = oy + ky - 1, ix = ox + kx - 1;
    float v = 0.f;
    if ((unsigned)iy < OHW && (unsigned)ix < OHW)
        v = g_y2a[(size_t)ic * NTOT + b * QQ + iy * OHW + ix];
    g_col2[idx] = v;
}

__global__ void im2col5_kernel()
{
    size_t idx = (size_t)blockIdx.x * blockDim.x + threadIdx.x;
    if (idx >= (size_t)800 * NTOT) return;
    int n = (int)(idx % NTOT);
    int krow = (int)(idx / NTOT);
    int ic = krow / 25, kk = krow - ic * 25;
    int ky = kk / 5, kx = kk - ky * 5;
    int b = n / QQ, q = n - b * QQ;
    int oy = q / OHW, ox = q - oy * OHW;
    int iy = oy + ky - 2, ix = ox + kx - 2;
    float v = 0.f;
    if ((unsigned)iy < OHW && (unsigned)ix < OHW)
        v = g_y3a[(size_t)ic * NTOT + b * QQ + iy * OHW + ix];
    g_col3[idx] = v;
}

__global__ void bnstats_kernel()
{
    int c = blockIdx.x;
    int t = threadIdx.x;
    const float* row = g_y + (size_t)c * NTOT;
    double s = 0.0, s2 = 0.0;
    for (int e = t; e < NTOT; e += 256) {
        float v = row[e];
        s += (double)v;
        s2 += (double)v * (double)v;
    }
    __shared__ double sh[256], sh2[256];
    sh[t] = s; sh2[t] = s2;
    __syncthreads();
    for (int off = 128; off; off >>= 1) {
        if (t < off) { sh[t] += sh[t + off]; sh2[t] += sh2[t + off]; }
        __syncthreads();
    }
    if (t == 0) {
        double mu = sh[0] / (double)NTOT;
        double var = sh2[0] / (double)NTOT - mu * mu;
        g_mean[c] = (float)mu;
        g_inv[c]  = (float)(1.0 / sqrt(var + 1e-5));
    }
}

__global__ void bnapply_kernel(const float* __restrict__ gamma,
                               const float* __restrict__ beta,
                               float* __restrict__ out)
{
    int idx = blockIdx.x * blockDim.x + threadIdx.x;   // (b, c, q) order
    if (idx >= BB * 512 * QQ) return;
    int q = idx % QQ;
    int t = idx / QQ;
    int c = t & 511;
    int b = t >> 9;
    float v = g_y[(size_t)c * NTOT + b * QQ + q];
    out[idx] = gamma[c] * (v - g_mean[c]) * g_inv[c] + beta[c];
}

// ====================== host side ==========================================
static float* symaddr(const void* sym)
{
    void* p = nullptr;
    cudaGetSymbolAddress(&p, sym);
    return (float*)p;
}

extern "C" void kernel_launch(void* const* d_in, const int* in_sizes, int n_in,
                              void* d_out, int out_size)
{
    const float* f1    = (const float*)d_in[0];
    const float* f2    = (const float*)d_in[1];
    const float* mask  = (const float*)d_in[2];
    const float* W1    = (const float*)d_in[3];
    const float* b1    = (const float*)d_in[4];
    const float* W2a   = (const float*)d_in[5];
    const float* b2a   = (const float*)d_in[6];
    const float* W2b   = (const float*)d_in[7];
    const float* b2b   = (const float*)d_in[8];
    const float* W3a   = (const float*)d_in[9];
    const float* b3a   = (const float*)d_in[10];
    const float* W3b   = (const float*)d_in[11];
    const float* b3b   = (const float*)d_in[12];
    const float* W4    = (const float*)d_in[13];
    const float* b4    = (const float*)d_in[14];
    const float* gamma = (const float*)d_in[15];
    const float* beta  = (const float*)d_in[16];
    float* out = (float*)d_out;

    float* p_f1r   = symaddr(g_f1r);
    float* p_f2r   = symaddr(g_f2r);
    float* p_cs    = symaddr(g_cs);
    float* p_corr  = symaddr(g_corr);
    float* p_corrp = symaddr(g_corrp);
    float* p_y     = symaddr(g_y);
    float* p_y2a   = symaddr(g_y2a);
    float* p_y3a   = symaddr(g_y3a);
    float* p_col2  = symaddr(g_col2);
    float* p_col3  = symaddr(g_col3);
    float* p_W1t   = symaddr(g_W1t);
    float* p_W2at  = symaddr(g_W2at);
    float* p_W3at  = symaddr(g_W3at);
    float* p_W4t   = symaddr(g_W4t);
    float* p_W2bt  = symaddr(g_W2bt);
    float* p_W3bt  = symaddr(g_W3bt);

    cudaFuncSetAttribute(gemm_tc, cudaFuncAttributeMaxDynamicSharedMemorySize,
                         GEMM_SMEM);

    const int T = 256;
    resize2_kernel<<<(2*BB*CC*QQ + T-1)/T, T>>>(f1, f2);
    maskpool_kernel<<<(NTOT + T-1)/T, T>>>(mask);

    transpose_kernel<<<(128*784 + T-1)/T, T>>>(W1,  p_W1t, 128, 784);
    transpose_kernel<<<(192*784 + T-1)/T, T>>>(W2a, p_W2at, 192, 784);
    transpose_kernel<<<(32*784  + T-1)/T, T>>>(W3a, p_W3at, 32, 784);
    transpose_kernel<<<(64*784  + T-1)/T, T>>>(W4,  p_W4t, 64, 784);
    transpose_kernel<<<(256*1728+ T-1)/T, T>>>(W2b, p_W2bt, 256, 1728);
    transpose_kernel<<<(64*800  + T-1)/T, T>>>(W3b, p_W3bt, 64, 800);

    // cost volume: corr[p, b*784+q] = relu(sum_c f1r[b,c,p]*f2r[b,c,q])
    {
        dim3 g(7, 7, BB);
        gemm_tc<<<g, 256, GEMM_SMEM>>>(p_f1r, (size_t)CC*QQ, QQ,
                                       p_f2r, (size_t)CC*QQ, QQ,
                                       p_corr, (size_t)QQ, NTOT,
                                       nullptr, nullptr, PP, QQ, CC);
    }
    colnorm_kernel<<<(NTOT + T-1)/T, T>>>();
    mp3_kernel<<<((size_t)PP*NTOT + T-1)/T, T>>>();

    // 1x1 branches (B scaled by cs on the fly)
    {
        dim3 g1(196, 1, 1), g2(196, 2, 1);
        gemm_tc<<<g1, 256, GEMM_SMEM>>>(p_W1t, 0, 128, p_corr, 0, NTOT,
                                        p_y, 0, NTOT, b1, p_cs, 128, NTOT, 784);
        gemm_tc<<<g2, 256, GEMM_SMEM>>>(p_W2at, 0, 192, p_corr, 0, NTOT,
                                        p_y2a, 0, NTOT, b2a, p_cs, 192, NTOT, 784);
        gemm_tc<<<g1, 256, GEMM_SMEM>>>(p_W3at, 0, 32, p_corr, 0, NTOT,
                                        p_y3a, 0, NTOT, b3a, p_cs, 32, NTOT, 784);
        gemm_tc<<<g1, 256, GEMM_SMEM>>>(p_W4t, 0, 64, p_corrp, 0, NTOT,
                                        p_y + (size_t)448*NTOT, 0, NTOT,
                                        b4, nullptr, 64, NTOT, 784);
    }

    // 3x3 conv 192->256
    im2col3_kernel<<<(int)(((size_t)1728*NTOT + T-1)/T), T>>>();
    {
        dim3 g(196, 2, 1);
        gemm_tc<<<g, 256, GEMM_SMEM>>>(p_W2bt, 0, 256, p_col2, 0, NTOT,
                                       p_y + (size_t)128*NTOT, 0, NTOT,
                                       b2b, nullptr, 256, NTOT, 1728);
    }
    // 5x5 conv 32->64
    im2col5_kernel<<<(int)(((size_t)800*NTOT + T-1)/T), T>>>();
    {
        dim3 g(196, 1, 1);
        gemm_tc<<<g, 256, GEMM_SMEM>>>(p_W3bt, 0, 64, p_col3, 0, NTOT,
                                       p_y + (size_t)384*NTOT, 0, NTOT,
                                       b3b, nullptr, 64, NTOT, 800);
    }

    bnstats_kernel<<<512, 256>>>();
    bnapply_kernel<<<(BB*512*QQ + T-1)/T, T>>>(gamma, beta, out);
}

// round 13
// speedup vs baseline: 1.1359x; 1.0575x over previous
#include <cuda_runtime.h>
#include <cuda_bf16.h>
#include <cstdint>
#include <math.h>

// ---------------- problem constants ----------------
#define BB   32
#define CC   256
#define HH   56
#define OHW  28
#define QQ   784
#define PP   784
#define NTOT (BB*QQ)   // 25088
#define NT4  (NTOT/4)  // 6272

// ---------------- scratch (static device arrays) ---------------------------
__device__ float g_f1r[(size_t)BB*CC*QQ];
__device__ float g_f2r[(size_t)BB*CC*QQ];
__device__ float g_mp [NTOT];
__device__ float g_cs [NTOT];                 // mask * rsqrt(norm2)
__device__ float g_corr [(size_t)PP*NTOT];    // (p, n)
__device__ float g_corrp[(size_t)PP*NTOT];    // scaled+maxpooled (p, n)
__device__ float g_y   [(size_t)512*NTOT];    // (c, n) concat pre-BN
__device__ float g_y2a [(size_t)192*NTOT];
__device__ float g_y3a [(size_t)32*NTOT];
__device__ float g_col2[(size_t)1728*NTOT];
__device__ float g_col3[(size_t)800*NTOT];
__device__ float g_W1t [784*128];
__device__ float g_W2at[784*192];
__device__ float g_W3at[784*32];
__device__ float g_W4t [784*64];
__device__ float g_W2bt[1728*256];
__device__ float g_W3bt[800*64];
__device__ float g_mean[512];
__device__ float g_inv [512];

// ====================== warp-MMA GEMM (mma.sync bf16) ======================
// O[m,n] = relu( sum_k A[k,m]*B[k,n]*(cs?cs[n]:1) + bias[m] )
// A,B K-major fp32 in gmem. Split into bf16 hi+lo; Ah*Bh + Ah*Bl + Al*Bh,
// fp32 accumulators (rel err ~1e-5).
#define TILE 128
#define KC   32
#define RSB  80                   // smem row stride bytes (32 bf16 + 8 pad)
#define ASZ  (128*RSB)            // 10240 B per matrix tile
#define STAGE (4*ASZ)             // Ah, Al, Bh, Bl
#define GEMM_SMEM (2*STAGE)       // double buffered = 81920 B

__device__ __forceinline__ uint32_t smem_u32(const void* p) {
    return (uint32_t)__cvta_generic_to_shared((void*)p);
}

__device__ __forceinline__ void cvt_pack(float v0, float v1,
                                         uint32_t& hi, uint32_t& lo) {
    __nv_bfloat16 h0 = __float2bfloat16(v0);
    __nv_bfloat16 h1 = __float2bfloat16(v1);
    __nv_bfloat16 l0 = __float2bfloat16(v0 - __bfloat162float(h0));
    __nv_bfloat16 l1 = __float2bfloat16(v1 - __bfloat162float(h1));
    hi = (uint32_t)__bfloat16_as_ushort(h0) | ((uint32_t)__bfloat16_as_ushort(h1) << 16);
    lo = (uint32_t)__bfloat16_as_ushort(l0) | ((uint32_t)__bfloat16_as_ushort(l1) << 16);
}

__device__ __forceinline__ void ldm_x4(uint32_t* r, uint32_t a) {
    asm volatile("ldmatrix.sync.aligned.m8n8.x4.shared.b16 {%0,%1,%2,%3}, [%4];"
                 : "=r"(r[0]), "=r"(r[1]), "=r"(r[2]), "=r"(r[3]) : "r"(a));
}

__device__ __forceinline__ void mma_bf16(float* c, const uint32_t* a,
                                         uint32_t b0, uint32_t b1) {
    asm volatile(
        "mma.sync.aligned.m16n8k16.row.col.f32.bf16.bf16.f32 "
        "{%0,%1,%2,%3}, {%4,%5,%6,%7}, {%8,%9}, {%0,%1,%2,%3};"
        : "+f"(c[0]), "+f"(c[1]), "+f"(c[2]), "+f"(c[3])
        : "r"(a[0]), "r"(a[1]), "r"(a[2]), "r"(a[3]), "r"(b0), "r"(b1));
}

__device__ void fill_stage(char* st,
    const float* __restrict__ A, int lda, int m0, int M,
    const float* __restrict__ B, int ldb, int n0, int N,
    const float* __restrict__ cs, int k0, int K)
{
    int tid = threadIdx.x;
#pragma unroll
    for (int i = 0; i < 8; i++) {
        int idx = (i << 8) + tid;          // 0..2047
        int r   = idx & 127;               // row (m or n) — coalesced
        int kp  = idx >> 7;                // k-pair 0..15
        int k   = k0 + (kp << 1);
        uint32_t off = (uint32_t)(r * RSB + (kp << 2));
        float a0 = 0.f, a1 = 0.f;
        int gm = m0 + r;
        if (gm < M) {
            if (k     < K) a0 = A[(size_t)k * lda + gm];
            if (k + 1 < K) a1 = A[(size_t)(k + 1) * lda + gm];
        }
        uint32_t hi, lo;
        cvt_pack(a0, a1, hi, lo);
        *(uint32_t*)(st + off)           = hi;
        *(uint32_t*)(st + ASZ + off)     = lo;
        float b0 = 0.f, b1 = 0.f;
        int gn = n0 + r;
        if (gn < N) {
            float sc = cs ? cs[gn] : 1.f;
            if (k     < K) b0 = B[(size_t)k * ldb + gn] * sc;
            if (k + 1 < K) b1 = B[(size_t)(k + 1) * ldb + gn] * sc;
        }
        cvt_pack(b0, b1, hi, lo);
        *(uint32_t*)(st + 2 * ASZ + off) = hi;
        *(uint32_t*)(st + 3 * ASZ + off) = lo;
    }
}

__global__ __launch_bounds__(256, 2)
void gemm_tc(const float* __restrict__ A, size_t sA, int lda,
             const float* __restrict__ B, size_t sB, int ldb,
             float* __restrict__ O, size_t sO, int ldo,
             const float* __restrict__ bias,
             const float* __restrict__ cs,
             int M, int N, int K)
{
    extern __shared__ char smem[];
    int bz = blockIdx.z;
    A += (size_t)bz * sA; B += (size_t)bz * sB; O += (size_t)bz * sO;
    int m0 = blockIdx.y * TILE, n0 = blockIdx.x * TILE;
    int tid = threadIdx.x, wid = tid >> 5, lane = tid & 31;

    int wm = (wid >> 1) << 5;     // warp m offset: 0,32,64,96
    int wn = (wid & 1) << 6;      // warp n offset: 0,64
    int quad = lane >> 3, li = lane & 7;
    int aRow = (quad & 1) * 8 + li;
    int aK   = (quad >> 1) * 8;
    int bRow = (quad >> 1) * 8 + li;
    int bK   = (quad & 1) * 8;

    float acc[2][8][4];
#pragma unroll
    for (int a = 0; a < 2; a++)
#pragma unroll
        for (int b = 0; b < 8; b++)
#pragma unroll
            for (int c = 0; c < 4; c++) acc[a][b][c] = 0.f;

    int nch = (K + KC - 1) / KC;
    fill_stage(smem, A, lda, m0, M, B, ldb, n0, N, cs, 0, K);
    __syncthreads();

    for (int ic = 0; ic < nch; ic++) {
        char* st = smem + (ic & 1) * STAGE;
        if (ic + 1 < nch)
            fill_stage(smem + ((ic + 1) & 1) * STAGE,
                       A, lda, m0, M, B, ldb, n0, N, cs, (ic + 1) * KC, K);

        uint32_t Ah = smem_u32(st);
        uint32_t Al = Ah + ASZ, Bh = Ah + 2 * ASZ, Bl = Ah + 3 * ASZ;
#pragma unroll
        for (int ks = 0; ks < 2; ks++) {
            uint32_t ah[2][4], al[2][4];
#pragma unroll
            for (int mf = 0; mf < 2; mf++) {
                uint32_t ra = (uint32_t)((wm + mf * 16 + aRow) * RSB +
                                         (ks * 16 + aK) * 2);
                ldm_x4(ah[mf], Ah + ra);
                ldm_x4(al[mf], Al + ra);
            }
#pragma unroll
            for (int p = 0; p < 4; p++) {
                uint32_t rb = (uint32_t)((wn + p * 16 + bRow) * RSB +
                                         (ks * 16 + bK) * 2);
                uint32_t bh[4], bl[4];
                ldm_x4(bh, Bh + rb);
                ldm_x4(bl, Bl + rb);
                // product-major ordering: same-acc chains spaced 4 apart
#pragma unroll
                for (int mf = 0; mf < 2; mf++) {
                    mma_bf16(acc[mf][2 * p],     ah[mf], bh[0], bh[1]);
                    mma_bf16(acc[mf][2 * p + 1], ah[mf], bh[2], bh[3]);
                }
#pragma unroll
                for (int mf = 0; mf < 2; mf++) {
                    mma_bf16(acc[mf][2 * p],     ah[mf], bl[0], bl[1]);
                    mma_bf16(acc[mf][2 * p + 1], ah[mf], bl[2], bl[3]);
                }
#pragma unroll
                for (int mf = 0; mf < 2; mf++) {
                    mma_bf16(acc[mf][2 * p],     al[mf], bh[0], bh[1]);
                    mma_bf16(acc[mf][2 * p + 1], al[mf], bh[2], bh[3]);
                }
            }
        }
        __syncthreads();
    }

    // epilogue: bias + relu, fragment scatter
#pragma unroll
    for (int mf = 0; mf < 2; mf++) {
        int mb = m0 + wm + mf * 16 + (lane >> 2);
#pragma unroll
        for (int half = 0; half < 2; half++) {
            int m = mb + half * 8;
            if (m >= M) continue;
            float bv = bias ? bias[m] : 0.f;
            float* orow = O + (size_t)m * ldo;
#pragma unroll
            for (int nf = 0; nf < 8; nf++) {
                int n = n0 + wn + nf * 8 + ((lane & 3) << 1);
                float v0 = fmaxf(acc[mf][nf][half * 2 + 0] + bv, 0.f);
                float v1 = fmaxf(acc[mf][nf][half * 2 + 1] + bv, 0.f);
                if (n < N)     orow[n]     = v0;
                if (n + 1 < N) orow[n + 1] = v1;
            }
        }
    }
}

// ====================== elementwise kernels ================================
// All 6 weight transposes in one kernel.
__global__ void transpose_all_kernel(
    const float* __restrict__ W1,  float* __restrict__ W1t,
    const float* __restrict__ W2a, float* __restrict__ W2at,
    const float* __restrict__ W3a, float* __restrict__ W3at,
    const float* __restrict__ W4,  float* __restrict__ W4t,
    const float* __restrict__ W2b, float* __restrict__ W2bt,
    const float* __restrict__ W3b, float* __restrict__ W3bt)
{
    int idx = blockIdx.x * blockDim.x + threadIdx.x;
    const float* in; float* out; int M, K; int base;
    if      (idx < 100352) { in=W1;  out=W1t;  M=128; K=784;  base=0; }
    else if (idx < 250880) { in=W2a; out=W2at; M=192; K=784;  base=100352; }
    else if (idx < 275968) { in=W3a; out=W3at; M=32;  K=784;  base=250880; }
    else if (idx < 326144) { in=W4;  out=W4t;  M=64;  K=784;  base=275968; }
    else if (idx < 768512) { in=W2b; out=W2bt; M=256; K=1728; base=326144; }
    else if (idx < 819712) { in=W3b; out=W3bt; M=64;  K=800;  base=768512; }
    else return;
    int i = idx - base;
    int m = i / K, k = i - m * K;
    out[k * M + m] = in[i];
}

__global__ void resize2_kernel(const float* __restrict__ f1,
                               const float* __restrict__ f2)
{
    int idx = blockIdx.x * blockDim.x + threadIdx.x;
    const int TOT = BB * CC * QQ;
    if (idx >= 2 * TOT) return;
    const float* src = f1; float* dst = g_f1r;
    int i = idx;
    if (i >= TOT) { i -= TOT; src = f2; dst = g_f2r; }
    int q = i % QQ;
    int r = i / QQ;
    int oy = q / OHW, ox = q % OHW;
    const float s = 55.0f / 27.0f;
    float fy = oy * s, fx = ox * s;
    int y0 = (int)fy; float wy = fy - (float)y0; int y1 = min(y0 + 1, HH - 1);
    int x0 = (int)fx; float wx = fx - (float)x0; int x1 = min(x0 + 1, HH - 1);
    const float* p = src + (size_t)r * HH * HH;
    float v00 = p[y0 * HH + x0], v01 = p[y0 * HH + x1];
    float v10 = p[y1 * HH + x0], v11 = p[y1 * HH + x1];
    float r0 = v00 * (1.f - wy) + v10 * wy;
    float r1 = v01 * (1.f - wy) + v11 * wy;
    dst[i] = r0 * (1.f - wx) + r1 * wx;
}

__global__ void maskpool_kernel(const float* __restrict__ m)
{
    int idx = blockIdx.x * blockDim.x + threadIdx.x;
    if (idx >= NTOT) return;
    int b = idx / QQ, q = idx % QQ;
    int oy = q / OHW, ox = q % OHW;
    const float* p = m + (size_t)b * HH * HH;
    int y = oy * 2, x = ox * 2;
    g_mp[idx] = fmaxf(fmaxf(p[y*HH+x], p[y*HH+x+1]),
                      fmaxf(p[(y+1)*HH+x], p[(y+1)*HH+x+1]));
}

// cs[n] = mp[n] * rsqrt(sum_p corr[p,n]^2)
__global__ void colnorm_kernel()
{
    int n = blockIdx.x * blockDim.x + threadIdx.x;
    if (n >= NTOT) return;
    const float* p = g_corr + n;
    float s = 0.f;
#pragma unroll 8
    for (int pp = 0; pp < PP; pp++) {
        float v = p[(size_t)pp * NTOT];
        s = fmaf(v, v, s);
    }
    g_cs[n] = g_mp[n] * rsqrtf(s);
}

// corrp[p,n] = max over 3x3 spatial nbhd of corr[p,.]*cs[.]
// 4 outputs per thread; 4-aligned q never crosses a row (ox%4==0, ox<=24).
__global__ void mp3_kernel()
{
    int idx = blockIdx.x * blockDim.x + threadIdx.x;
    if (idx >= PP * NT4) return;
    int p = idx / NT4;
    int t = idx - p * NT4;
    int n0 = t << 2;
    int b = n0 / QQ, q = n0 - b * QQ;
    int oy = q / OHW, ox = q - oy * OHW;
    const float* base = g_corr + (size_t)p * NTOT + b * QQ;
    const float* csb  = g_cs + b * QQ;
    float w[3][6];
#pragma unroll
    for (int r = 0; r < 3; r++) {
        int y = oy - 1 + r;
        bool yok = (unsigned)y < OHW;
#pragma unroll
        for (int c = 0; c < 6; c++) {
            int x = ox - 1 + c;
            int qq = y * OHW + x;
            w[r][c] = (yok && (unsigned)x < OHW) ? base[qq] * csb[qq] : -1e30f;
        }
    }
    float4 v;
    float* vp = &v.x;
#pragma unroll
    for (int i = 0; i < 4; i++) {
        float mx = -1e30f;
#pragma unroll
        for (int r = 0; r < 3; r++)
#pragma unroll
            for (int c = 0; c < 3; c++)
                mx = fmaxf(mx, w[r][i + c]);
        vp[i] = mx;
    }
    *(float4*)(g_corrp + (size_t)p * NTOT + n0) = v;
}

// im2col 3x3 pad1 from g_y2a: 4 outputs per thread, float4 store.
__global__ void im2col3_kernel()
{
    int idx = blockIdx.x * blockDim.x + threadIdx.x;
    if (idx >= 1728 * NT4) return;
    int krow = idx / NT4;
    int t = idx - krow * NT4;
    int n0 = t << 2;
    int ic = krow / 9, kk = krow - ic * 9;
    int ky = kk / 3 - 1, kx = kk - (kk / 3) * 3 - 1;
    int b = n0 / QQ, q = n0 - b * QQ;
    int oy = q / OHW, ox = q - oy * OHW;
    int iy = oy + ky;
    bool rowok = (unsigned)iy < OHW;
    const float* src = g_y2a + (size_t)ic * NTOT + b * QQ + iy * OHW;
    float4 v;
    float* vp = &v.x;
#pragma unroll
    for (int i = 0; i < 4; i++) {
        int ix = ox + kx + i;
        vp[i] = (rowok && (unsigned)ix < OHW) ? src[ix] : 0.f;
    }
    *(float4*)(g_col2 + (size_t)krow * NTOT + n0) = v;
}

// im2col 5x5 pad2 from g_y3a: 4 outputs per thread.
__global__ void im2col5_kernel()
{
    int idx = blockIdx.x * blockDim.x + threadIdx.x;
    if (idx >= 800 * NT4) return;
    int krow = idx / NT4;
    int t = idx - krow * NT4;
    int n0 = t << 2;
    int ic = krow / 25, kk = krow - ic * 25;
    int ky = kk / 5 - 2, kx = kk - (kk / 5) * 5 - 2;
    int b = n0 / QQ, q = n0 - b * QQ;
    int oy = q / OHW, ox = q - oy * OHW;
    int iy = oy + ky;
    bool rowok = (unsigned)iy < OHW;
    const float* src = g_y3a + (size_t)ic * NTOT + b * QQ + iy * OHW;
    float4 v;
    float* vp = &v.x;
#pragma unroll
    for (int i = 0; i < 4; i++) {
        int ix = ox + kx + i;
        vp[i] = (rowok && (unsigned)ix < OHW) ? src[ix] : 0.f;
    }
    *(float4*)(g_col3 + (size_t)krow * NTOT + n0) = v;
}

__global__ void bnstats_kernel()
{
    int c = blockIdx.x;
    int t = threadIdx.x;
    const float* row = g_y + (size_t)c * NTOT;
    double s = 0.0, s2 = 0.0;
    for (int e = t; e < NTOT; e += 256) {
        float v = row[e];
        s += (double)v;
        s2 += (double)v * (double)v;
    }
    __shared__ double sh[256], sh2[256];
    sh[t] = s; sh2[t] = s2;
    __syncthreads();
    for (int off = 128; off; off >>= 1) {
        if (t < off) { sh[t] += sh[t + off]; sh2[t] += sh2[t + off]; }
        __syncthreads();
    }
    if (t == 0) {
        double mu = sh[0] / (double)NTOT;
        double var = sh2[0] / (double)NTOT - mu * mu;
        g_mean[c] = (float)mu;
        g_inv[c]  = (float)(1.0 / sqrt(var + 1e-5));
    }
}

__global__ void bnapply_kernel(const float* __restrict__ gamma,
                               const float* __restrict__ beta,
                               float* __restrict__ out)
{
    int idx = blockIdx.x * blockDim.x + threadIdx.x;   // over BB*512*(QQ/4)
    if (idx >= BB * 512 * (QQ / 4)) return;
    int q4 = idx % (QQ / 4);
    int t = idx / (QQ / 4);
    int c = t & 511;
    int b = t >> 9;
    float4 v = *(const float4*)(g_y + (size_t)c * NTOT + b * QQ + q4 * 4);
    float g = gamma[c] * g_inv[c];
    float be = beta[c] - g_mean[c] * g;
    float4 o;
    o.x = g * v.x + be; o.y = g * v.y + be;
    o.z = g * v.z + be; o.w = g * v.w + be;
    *(float4*)(out + (size_t)idx * 4) = o;
}

// ====================== host side ==========================================
static float* symaddr(const void* sym)
{
    void* p = nullptr;
    cudaGetSymbolAddress(&p, sym);
    return (float*)p;
}

extern "C" void kernel_launch(void* const* d_in, const int* in_sizes, int n_in,
                              void* d_out, int out_size)
{
    const float* f1    = (const float*)d_in[0];
    const float* f2    = (const float*)d_in[1];
    const float* mask  = (const float*)d_in[2];
    const float* W1    = (const float*)d_in[3];
    const float* b1    = (const float*)d_in[4];
    const float* W2a   = (const float*)d_in[5];
    const float* b2a   = (const float*)d_in[6];
    const float* W2b   = (const float*)d_in[7];
    const float* b2b   = (const float*)d_in[8];
    const float* W3a   = (const float*)d_in[9];
    const float* b3a   = (const float*)d_in[10];
    const float* W3b   = (const float*)d_in[11];
    const float* b3b   = (const float*)d_in[12];
    const float* W4    = (const float*)d_in[13];
    const float* b4    = (const float*)d_in[14];
    const float* gamma = (const float*)d_in[15];
    const float* beta  = (const float*)d_in[16];
    float* out = (float*)d_out;

    float* p_f1r   = symaddr(g_f1r);
    float* p_f2r   = symaddr(g_f2r);
    float* p_cs    = symaddr(g_cs);
    float* p_corr  = symaddr(g_corr);
    float* p_corrp = symaddr(g_corrp);
    float* p_y     = symaddr(g_y);
    float* p_y2a   = symaddr(g_y2a);
    float* p_y3a   = symaddr(g_y3a);
    float* p_col2  = symaddr(g_col2);
    float* p_col3  = symaddr(g_col3);
    float* p_W1t   = symaddr(g_W1t);
    float* p_W2at  = symaddr(g_W2at);
    float* p_W3at  = symaddr(g_W3at);
    float* p_W4t   = symaddr(g_W4t);
    float* p_W2bt  = symaddr(g_W2bt);
    float* p_W3bt  = symaddr(g_W3bt);

    cudaFuncSetAttribute(gemm_tc, cudaFuncAttributeMaxDynamicSharedMemorySize,
                         GEMM_SMEM);

    const int T = 256;
    // 1: all weight transposes
    transpose_all_kernel<<<(819712 + T-1)/T, T>>>(W1, p_W1t, W2a, p_W2at,
                                                  W3a, p_W3at, W4, p_W4t,
                                                  W2b, p_W2bt, W3b, p_W3bt);
    // 2-3
    resize2_kernel<<<(2*BB*CC*QQ + T-1)/T, T>>>(f1, f2);
    maskpool_kernel<<<(NTOT + T-1)/T, T>>>(mask);

    // 4: cost volume corr[p, b*784+q] = relu(sum_c f1r[b,c,p]*f2r[b,c,q])
    {
        dim3 g(7, 7, BB);
        gemm_tc<<<g, 256, GEMM_SMEM>>>(p_f1r, (size_t)CC*QQ, QQ,
                                       p_f2r, (size_t)CC*QQ, QQ,
                                       p_corr, (size_t)QQ, NTOT,
                                       nullptr, nullptr, PP, QQ, CC);
    }
    // 5
    colnorm_kernel<<<(NTOT + T-1)/T, T>>>();

    // 6: y2a GEMM  <-- ncu -s 5 -c 1 captures this launch
    {
        dim3 g2(196, 2, 1);
        gemm_tc<<<g2, 256, GEMM_SMEM>>>(p_W2at, 0, 192, p_corr, 0, NTOT,
                                        p_y2a, 0, NTOT, b2a, p_cs, 192, NTOT, 784);
    }
    // 7-8: other 1x1 branches
    {
        dim3 g1(196, 1, 1);
        gemm_tc<<<g1, 256, GEMM_SMEM>>>(p_W1t, 0, 128, p_corr, 0, NTOT,
                                        p_y, 0, NTOT, b1, p_cs, 128, NTOT, 784);
        gemm_tc<<<g1, 256, GEMM_SMEM>>>(p_W3at, 0, 32, p_corr, 0, NTOT,
                                        p_y3a, 0, NTOT, b3a, p_cs, 32, NTOT, 784);
    }
    // 9-10: pooled branch
    mp3_kernel<<<(PP*NT4 + T-1)/T, T>>>();
    {
        dim3 g1(196, 1, 1);
        gemm_tc<<<g1, 256, GEMM_SMEM>>>(p_W4t, 0, 64, p_corrp, 0, NTOT,
                                        p_y + (size_t)448*NTOT, 0, NTOT,
                                        b4, nullptr, 64, NTOT, 784);
    }
    // 11-12: 3x3 conv 192->256
    im2col3_kernel<<<(1728*NT4 + T-1)/T, T>>>();
    {
        dim3 g(196, 2, 1);
        gemm_tc<<<g, 256, GEMM_SMEM>>>(p_W2bt, 0, 256, p_col2, 0, NTOT,
                                       p_y + (size_t)128*NTOT, 0, NTOT,
                                       b2b, nullptr, 256, NTOT, 1728);
    }
    // 13-14: 5x5 conv 32->64
    im2col5_kernel<<<(800*NT4 + T-1)/T, T>>>();
    {
        dim3 g(196, 1, 1);
        gemm_tc<<<g, 256, GEMM_SMEM>>>(p_W3bt, 0, 64, p_col3, 0, NTOT,
                                       p_y + (size_t)384*NTOT, 0, NTOT,
                                       b3b, nullptr, 64, NTOT, 800);
    }
    // 15-16: BatchNorm
    bnstats_kernel<<<512, 256>>>();
    bnapply_kernel<<<(BB*512*(QQ/4) + T-1)/T, T>>>(gamma, beta, out);
}

// round 16
// speedup vs baseline: 1.4525x; 1.2786x over previous
#include <cuda_runtime.h>
#include <cuda_bf16.h>
#include <cstdint>
#include <math.h>

// ---------------- problem constants ----------------
#define BB   32
#define CC   256
#define HH   56
#define OHW  28
#define QQ   784
#define PP   784
#define NTOT (BB*QQ)   // 25088
#define NT4  (NTOT/4)  // 6272
#define MCAT 352       // merged 1x1 output channels: 128+192+32

// ---------------- scratch (static device arrays) ---------------------------
__device__ float g_f1r[(size_t)BB*CC*QQ];
__device__ float g_f2r[(size_t)BB*CC*QQ];
__device__ float g_mp [NTOT];
__device__ float g_cs [NTOT];
__device__ float g_corr [(size_t)PP*NTOT];    // (p, n)
__device__ float g_corrp[(size_t)PP*NTOT];
__device__ float g_y   [(size_t)512*NTOT];    // channels 128..511 used
__device__ float g_ycat[(size_t)MCAT*NTOT];   // y1(0-127) y2a(128-319) y3a(320-351)
__device__ float g_col2[(size_t)1728*NTOT];
__device__ float g_col3[(size_t)800*NTOT];
__device__ float g_Wcat[784*MCAT];            // K-major merged 1x1 weights
__device__ float g_bcat[MCAT];
__device__ float g_W4t [784*64];
__device__ float g_W2bt[1728*256];
__device__ float g_W3bt[800*64];
__device__ float g_mean[512];
__device__ float g_inv [512];

// ====================== warp-MMA GEMM (mma.sync bf16) ======================
#define TILE 128
#define KC   32
#define RSB  80
#define ASZ  (128*RSB)
#define STAGE (4*ASZ)             // Ah, Al, Bh, Bl
#define GEMM_SMEM (2*STAGE)       // 81920 B

__device__ __forceinline__ uint32_t smem_u32(const void* p) {
    return (uint32_t)__cvta_generic_to_shared((void*)p);
}

__device__ __forceinline__ void cvt_pack(float v0, float v1,
                                         uint32_t& hi, uint32_t& lo) {
    __nv_bfloat16 h0 = __float2bfloat16(v0);
    __nv_bfloat16 h1 = __float2bfloat16(v1);
    __nv_bfloat16 l0 = __float2bfloat16(v0 - __bfloat162float(h0));
    __nv_bfloat16 l1 = __float2bfloat16(v1 - __bfloat162float(h1));
    hi = (uint32_t)__bfloat16_as_ushort(h0) | ((uint32_t)__bfloat16_as_ushort(h1) << 16);
    lo = (uint32_t)__bfloat16_as_ushort(l0) | ((uint32_t)__bfloat16_as_ushort(l1) << 16);
}

__device__ __forceinline__ void ldm_x4(uint32_t* r, uint32_t a) {
    asm volatile("ldmatrix.sync.aligned.m8n8.x4.shared.b16 {%0,%1,%2,%3}, [%4];"
                 : "=r"(r[0]), "=r"(r[1]), "=r"(r[2]), "=r"(r[3]) : "r"(a));
}

__device__ __forceinline__ void mma_bf16(float* c, const uint32_t* a,
                                         uint32_t b0, uint32_t b1) {
    asm volatile(
        "mma.sync.aligned.m16n8k16.row.col.f32.bf16.bf16.f32 "
        "{%0,%1,%2,%3}, {%4,%5,%6,%7}, {%8,%9}, {%0,%1,%2,%3};"
        : "+f"(c[0]), "+f"(c[1]), "+f"(c[2]), "+f"(c[3])
        : "r"(a[0]), "r"(a[1]), "r"(a[2]), "r"(a[3]), "r"(b0), "r"(b1));
}

// Prologue-only full-stage fill (LDG+cvt+STS fused).
__device__ void fill_stage(char* st,
    const float* __restrict__ A, int lda, int m0, int M,
    const float* __restrict__ B, int ldb, int n0, int N,
    const float* __restrict__ cs, int k0, int K)
{
    int tid = threadIdx.x;
#pragma unroll
    for (int i = 0; i < 8; i++) {
        int idx = (i << 8) + tid;
        int r   = idx & 127;
        int kp  = idx >> 7;
        int k   = k0 + (kp << 1);
        uint32_t off = (uint32_t)(r * RSB + (kp << 2));
        float a0 = 0.f, a1 = 0.f;
        int gm = m0 + r;
        if (gm < M) {
            if (k     < K) a0 = A[(size_t)k * lda + gm];
            if (k + 1 < K) a1 = A[(size_t)(k + 1) * lda + gm];
        }
        uint32_t hi, lo;
        cvt_pack(a0, a1, hi, lo);
        *(uint32_t*)(st + off)           = hi;
        *(uint32_t*)(st + ASZ + off)     = lo;
        float b0 = 0.f, b1 = 0.f;
        int gn = n0 + r;
        if (gn < N) {
            float sc = cs ? cs[gn] : 1.f;
            if (k     < K) b0 = B[(size_t)k * ldb + gn] * sc;
            if (k + 1 < K) b1 = B[(size_t)(k + 1) * ldb + gn] * sc;
        }
        cvt_pack(b0, b1, hi, lo);
        *(uint32_t*)(st + 2 * ASZ + off) = hi;
        *(uint32_t*)(st + 3 * ASZ + off) = lo;
    }
}

// Pipelined fill: LDG half-chunk into registers (issued before mma section).
__device__ __forceinline__ void ldg_half(float2* ra, float2* rb, int half,
    const float* __restrict__ A, int lda, int m0, int M,
    const float* __restrict__ B, int ldb, int n0, int N,
    const float* __restrict__ cs, int k0, int K, int tid)
{
#pragma unroll
    for (int i = 0; i < 4; i++) {
        int idx = ((half * 4 + i) << 8) + tid;
        int r   = idx & 127;
        int kp  = idx >> 7;
        int k   = k0 + (kp << 1);
        float a0 = 0.f, a1 = 0.f;
        int gm = m0 + r;
        if (gm < M) {
            if (k     < K) a0 = A[(size_t)k * lda + gm];
            if (k + 1 < K) a1 = A[(size_t)(k + 1) * lda + gm];
        }
        ra[i] = make_float2(a0, a1);
        float b0 = 0.f, b1 = 0.f;
        int gn = n0 + r;
        if (gn < N) {
            float sc = cs ? cs[gn] : 1.f;
            if (k     < K) b0 = B[(size_t)k * ldb + gn] * sc;
            if (k + 1 < K) b1 = B[(size_t)(k + 1) * ldb + gn] * sc;
        }
        rb[i] = make_float2(b0, b1);
    }
}

// Pipelined fill: cvt + STS half-chunk (consumed after mma section).
__device__ __forceinline__ void sts_half(char* st, const float2* ra,
                                         const float2* rb, int half, int tid)
{
#pragma unroll
    for (int i = 0; i < 4; i++) {
        int idx = ((half * 4 + i) << 8) + tid;
        int r   = idx & 127;
        int kp  = idx >> 7;
        uint32_t off = (uint32_t)(r * RSB + (kp << 2));
        uint32_t hi, lo;
        cvt_pack(ra[i].x, ra[i].y, hi, lo);
        *(uint32_t*)(st + off)           = hi;
        *(uint32_t*)(st + ASZ + off)     = lo;
        cvt_pack(rb[i].x, rb[i].y, hi, lo);
        *(uint32_t*)(st + 2 * ASZ + off) = hi;
        *(uint32_t*)(st + 3 * ASZ + off) = lo;
    }
}

__global__ __launch_bounds__(256, 2)
void gemm_tc(const float* __restrict__ A, size_t sA, int lda,
             const float* __restrict__ B, size_t sB, int ldb,
             float* __restrict__ O, size_t sO, int ldo,
             const float* __restrict__ bias,
             const float* __restrict__ cs,
             int M, int N, int K)
{
    extern __shared__ char smem[];
    int bz = blockIdx.z;
    A += (size_t)bz * sA; B += (size_t)bz * sB; O += (size_t)bz * sO;
    int m0 = blockIdx.y * TILE, n0 = blockIdx.x * TILE;
    int tid = threadIdx.x, wid = tid >> 5, lane = tid & 31;

    int wm = (wid >> 1) << 5;
    int wn = (wid & 1) << 6;
    int quad = lane >> 3, li = lane & 7;
    int aRow = (quad & 1) * 8 + li;
    int aK   = (quad >> 1) * 8;
    int bRow = (quad >> 1) * 8 + li;
    int bK   = (quad & 1) * 8;

    float acc[2][8][4];
#pragma unroll
    for (int a = 0; a < 2; a++)
#pragma unroll
        for (int b = 0; b < 8; b++)
#pragma unroll
            for (int c = 0; c < 4; c++) acc[a][b][c] = 0.f;

    int nch = (K + KC - 1) / KC;
    fill_stage(smem, A, lda, m0, M, B, ldb, n0, N, cs, 0, K);
    __syncthreads();

    for (int ic = 0; ic < nch; ic++) {
        char* st = smem + (ic & 1) * STAGE;
        char* nx = smem + ((ic + 1) & 1) * STAGE;
        bool pf = (ic + 1 < nch);
        int kn = (ic + 1) * KC;

        uint32_t Ah = smem_u32(st);
        uint32_t Al = Ah + ASZ, Bh = Ah + 2 * ASZ, Bl = Ah + 3 * ASZ;
#pragma unroll
        for (int ks = 0; ks < 2; ks++) {
            float2 ra[4], rb[4];
            if (pf) ldg_half(ra, rb, ks, A, lda, m0, M, B, ldb, n0, N,
                             cs, kn, K, tid);    // LDG issued; consumed after mma

            uint32_t ah[2][4], al[2][4];
#pragma unroll
            for (int mf = 0; mf < 2; mf++) {
                uint32_t raddr = (uint32_t)((wm + mf * 16 + aRow) * RSB +
                                            (ks * 16 + aK) * 2);
                ldm_x4(ah[mf], Ah + raddr);
                ldm_x4(al[mf], Al + raddr);
            }
#pragma unroll
            for (int p = 0; p < 4; p++) {
                uint32_t rbad = (uint32_t)((wn + p * 16 + bRow) * RSB +
                                           (ks * 16 + bK) * 2);
                uint32_t bh[4], bl[4];
                ldm_x4(bh, Bh + rbad);
                ldm_x4(bl, Bl + rbad);
#pragma unroll
                for (int mf = 0; mf < 2; mf++) {
                    mma_bf16(acc[mf][2 * p],     ah[mf], bh[0], bh[1]);
                    mma_bf16(acc[mf][2 * p + 1], ah[mf], bh[2], bh[3]);
                }
#pragma unroll
                for (int mf = 0; mf < 2; mf++) {
                    mma_bf16(acc[mf][2 * p],     ah[mf], bl[0], bl[1]);
                    mma_bf16(acc[mf][2 * p + 1], ah[mf], bl[2], bl[3]);
                }
#pragma unroll
                for (int mf = 0; mf < 2; mf++) {
                    mma_bf16(acc[mf][2 * p],     al[mf], bh[0], bh[1]);
                    mma_bf16(acc[mf][2 * p + 1], al[mf], bh[2], bh[3]);
                }
            }
            if (pf) sts_half(nx, ra, rb, ks, tid);
        }
        __syncthreads();
    }

    // epilogue: bias + relu, fragment scatter
#pragma unroll
    for (int mf = 0; mf < 2; mf++) {
        int mb = m0 + wm + mf * 16 + (lane >> 2);
#pragma unroll
        for (int half = 0; half < 2; half++) {
            int m = mb + half * 8;
            if (m >= M) continue;
            float bv = bias ? bias[m] : 0.f;
            float* orow = O + (size_t)m * ldo;
#pragma unroll
            for (int nf = 0; nf < 8; nf++) {
                int n = n0 + wn + nf * 8 + ((lane & 3) << 1);
                float v0 = fmaxf(acc[mf][nf][half * 2 + 0] + bv, 0.f);
                float v1 = fmaxf(acc[mf][nf][half * 2 + 1] + bv, 0.f);
                if (n < N)     orow[n]     = v0;
                if (n + 1 < N) orow[n + 1] = v1;
            }
        }
    }
}

// ====================== elementwise kernels ================================
// Weight transposes (merged 1x1 weights into Wcat) + bias concat.
__global__ void transpose_all_kernel(
    const float* __restrict__ W1,  const float* __restrict__ W2a,
    const float* __restrict__ W3a, const float* __restrict__ W4,
    const float* __restrict__ W2b, const float* __restrict__ W3b,
    const float* __restrict__ b1,  const float* __restrict__ b2a,
    const float* __restrict__ b3a,
    float* __restrict__ Wcat, float* __restrict__ bcat,
    float* __restrict__ W4t, float* __restrict__ W2bt,
    float* __restrict__ W3bt)
{
    int idx = blockIdx.x * blockDim.x + threadIdx.x;
    if (idx < 100352) {                       // W1 -> Wcat[.., 0..127]
        int m = idx / 784, k = idx - m * 784;
        Wcat[k * MCAT + m] = W1[idx];
    } else if (idx < 250880) {                // W2a -> Wcat[.., 128..319]
        int i = idx - 100352;
        int m = i / 784, k = i - m * 784;
        Wcat[k * MCAT + 128 + m] = W2a[i];
    } else if (idx < 275968) {                // W3a -> Wcat[.., 320..351]
        int i = idx - 250880;
        int m = i / 784, k = i - m * 784;
        Wcat[k * MCAT + 320 + m] = W3a[i];
    } else if (idx < 326144) {                // W4
        int i = idx - 275968;
        int m = i / 784, k = i - m * 784;
        W4t[k * 64 + m] = W4[i];
    } else if (idx < 768512) {                // W2b
        int i = idx - 326144;
        int m = i / 1728, k = i - m * 1728;
        W2bt[k * 256 + m] = W2b[i];
    } else if (idx < 819712) {                // W3b
        int i = idx - 768512;
        int m = i / 800, k = i - m * 800;
        W3bt[k * 64 + m] = W3b[i];
    } else if (idx < 819712 + MCAT) {         // bias concat
        int i = idx - 819712;
        bcat[i] = (i < 128) ? b1[i] : (i < 320) ? b2a[i - 128] : b3a[i - 320];
    }
}

__global__ void resize2_kernel(const float* __restrict__ f1,
                               const float* __restrict__ f2)
{
    int idx = blockIdx.x * blockDim.x + threadIdx.x;
    const int TOT = BB * CC * QQ;
    if (idx >= 2 * TOT) return;
    const float* src = f1; float* dst = g_f1r;
    int i = idx;
    if (i >= TOT) { i -= TOT; src = f2; dst = g_f2r; }
    int q = i % QQ;
    int r = i / QQ;
    int oy = q / OHW, ox = q % OHW;
    const float s = 55.0f / 27.0f;
    float fy = oy * s, fx = ox * s;
    int y0 = (int)fy; float wy = fy - (float)y0; int y1 = min(y0 + 1, HH - 1);
    int x0 = (int)fx; float wx = fx - (float)x0; int x1 = min(x0 + 1, HH - 1);
    const float* p = src + (size_t)r * HH * HH;
    float v00 = p[y0 * HH + x0], v01 = p[y0 * HH + x1];
    float v10 = p[y1 * HH + x0], v11 = p[y1 * HH + x1];
    float r0 = v00 * (1.f - wy) + v10 * wy;
    float r1 = v01 * (1.f - wy) + v11 * wy;
    dst[i] = r0 * (1.f - wx) + r1 * wx;
}

__global__ void maskpool_kernel(const float* __restrict__ m)
{
    int idx = blockIdx.x * blockDim.x + threadIdx.x;
    if (idx >= NTOT) return;
    int b = idx / QQ, q = idx % QQ;
    int oy = q / OHW, ox = q % OHW;
    const float* p = m + (size_t)b * HH * HH;
    int y = oy * 2, x = ox * 2;
    g_mp[idx] = fmaxf(fmaxf(p[y*HH+x], p[y*HH+x+1]),
                      fmaxf(p[(y+1)*HH+x], p[(y+1)*HH+x+1]));
}

__global__ void colnorm_kernel()
{
    int n = blockIdx.x * blockDim.x + threadIdx.x;
    if (n >= NTOT) return;
    const float* p = g_corr + n;
    float s = 0.f;
#pragma unroll 8
    for (int pp = 0; pp < PP; pp++) {
        float v = p[(size_t)pp * NTOT];
        s = fmaf(v, v, s);
    }
    g_cs[n] = g_mp[n] * rsqrtf(s);
}

__global__ void mp3_kernel()
{
    int idx = blockIdx.x * blockDim.x + threadIdx.x;
    if (idx >= PP * NT4) return;
    int p = idx / NT4;
    int t = idx - p * NT4;
    int n0 = t << 2;
    int b = n0 / QQ, q = n0 - b * QQ;
    int oy = q / OHW, ox = q - oy * OHW;
    const float* base = g_corr + (size_t)p * NTOT + b * QQ;
    const float* csb  = g_cs + b * QQ;
    float w[3][6];
#pragma unroll
    for (int r = 0; r < 3; r++) {
        int y = oy - 1 + r;
        bool yok = (unsigned)y < OHW;
#pragma unroll
        for (int c = 0; c < 6; c++) {
            int x = ox - 1 + c;
            int qq = y * OHW + x;
            w[r][c] = (yok && (unsigned)x < OHW) ? base[qq] * csb[qq] : -1e30f;
        }
    }
    float4 v;
    float* vp = &v.x;
#pragma unroll
    for (int i = 0; i < 4; i++) {
        float mx = -1e30f;
#pragma unroll
        for (int r = 0; r < 3; r++)
#pragma unroll
            for (int c = 0; c < 3; c++)
                mx = fmaxf(mx, w[r][i + c]);
        vp[i] = mx;
    }
    *(float4*)(g_corrp + (size_t)p * NTOT + n0) = v;
}

// im2col 3x3 pad1 from y2a (= g_ycat rows 128..319)
__global__ void im2col3_kernel()
{
    int idx = blockIdx.x * blockDim.x + threadIdx.x;
    if (idx >= 1728 * NT4) return;
    int krow = idx / NT4;
    int t = idx - krow * NT4;
    int n0 = t << 2;
    int ic = krow / 9, kk = krow - ic * 9;
    int ky = kk / 3 - 1, kx = kk - (kk / 3) * 3 - 1;
    int b = n0 / QQ, q = n0 - b * QQ;
    int oy = q / OHW, ox = q - oy * OHW;
    int iy = oy + ky;
    bool rowok = (unsigned)iy < OHW;
    const float* src = g_ycat + (size_t)(128 + ic) * NTOT + b * QQ + iy * OHW;
    float4 v;
    float* vp = &v.x;
#pragma unroll
    for (int i = 0; i < 4; i++) {
        int ix = ox + kx + i;
        vp[i] = (rowok && (unsigned)ix < OHW) ? src[ix] : 0.f;
    }
    *(float4*)(g_col2 + (size_t)krow * NTOT + n0) = v;
}

// im2col 5x5 pad2 from y3a (= g_ycat rows 320..351)
__global__ void im2col5_kernel()
{
    int idx = blockIdx.x * blockDim.x + threadIdx.x;
    if (idx >= 800 * NT4) return;
    int krow = idx / NT4;
    int t = idx - krow * NT4;
    int n0 = t << 2;
    int ic = krow / 25, kk = krow - ic * 25;
    int ky = kk / 5 - 2, kx = kk - (kk / 5) * 5 - 2;
    int b = n0 / QQ, q = n0 - b * QQ;
    int oy = q / OHW, ox = q - oy * OHW;
    int iy = oy + ky;
    bool rowok = (unsigned)iy < OHW;
    const float* src = g_ycat + (size_t)(320 + ic) * NTOT + b * QQ + iy * OHW;
    float4 v;
    float* vp = &v.x;
#pragma unroll
    for (int i = 0; i < 4; i++) {
        int ix = ox + kx + i;
        vp[i] = (rowok && (unsigned)ix < OHW) ? src[ix] : 0.f;
    }
    *(float4*)(g_col3 + (size_t)krow * NTOT + n0) = v;
}

__global__ void bnstats_kernel()
{
    int c = blockIdx.x;
    int t = threadIdx.x;
    const float* row = (c < 128) ? g_ycat + (size_t)c * NTOT
                                 : g_y + (size_t)c * NTOT;
    double s = 0.0, s2 = 0.0;
    for (int e = t; e < NTOT; e += 256) {
        float v = row[e];
        s += (double)v;
        s2 += (double)v * (double)v;
    }
    __shared__ double sh[256], sh2[256];
    sh[t] = s; sh2[t] = s2;
    __syncthreads();
    for (int off = 128; off; off >>= 1) {
        if (t < off) { sh[t] += sh[t + off]; sh2[t] += sh2[t + off]; }
        __syncthreads();
    }
    if (t == 0) {
        double mu = sh[0] / (double)NTOT;
        double var = sh2[0] / (double)NTOT - mu * mu;
        g_mean[c] = (float)mu;
        g_inv[c]  = (float)(1.0 / sqrt(var + 1e-5));
    }
}

__global__ void bnapply_kernel(const float* __restrict__ gamma,
                               const float* __restrict__ beta,
                               float* __restrict__ out)
{
    int idx = blockIdx.x * blockDim.x + threadIdx.x;
    if (idx >= BB * 512 * (QQ / 4)) return;
    int q4 = idx % (QQ / 4);
    int t = idx / (QQ / 4);
    int c = t & 511;
    int b = t >> 9;
    const float* src = (c < 128) ? g_ycat + (size_t)c * NTOT
                                 : g_y + (size_t)c * NTOT;
    float4 v = *(const float4*)(src + b * QQ + q4 * 4);
    float g = gamma[c] * g_inv[c];
    float be = beta[c] - g_mean[c] * g;
    float4 o;
    o.x = g * v.x + be; o.y = g * v.y + be;
    o.z = g * v.z + be; o.w = g * v.w + be;
    *(float4*)(out + (size_t)idx * 4) = o;
}

// ====================== host side ==========================================
static float* symaddr(const void* sym)
{
    void* p = nullptr;
    cudaGetSymbolAddress(&p, sym);
    return (float*)p;
}

extern "C" void kernel_launch(void* const* d_in, const int* in_sizes, int n_in,
                              void* d_out, int out_size)
{
    const float* f1    = (const float*)d_in[0];
    const float* f2    = (const float*)d_in[1];
    const float* mask  = (const float*)d_in[2];
    const float* W1    = (const float*)d_in[3];
    const float* b1    = (const float*)d_in[4];
    const float* W2a   = (const float*)d_in[5];
    const float* b2a   = (const float*)d_in[6];
    const float* W2b   = (const float*)d_in[7];
    const float* b2b   = (const float*)d_in[8];
    const float* W3a   = (const float*)d_in[9];
    const float* b3a   = (const float*)d_in[10];
    const float* W3b   = (const float*)d_in[11];
    const float* b3b   = (const float*)d_in[12];
    const float* W4    = (const float*)d_in[13];
    const float* b4    = (const float*)d_in[14];
    const float* gamma = (const float*)d_in[15];
    const float* beta  = (const float*)d_in[16];
    float* out = (float*)d_out;

    float* p_f1r   = symaddr(g_f1r);
    float* p_f2r   = symaddr(g_f2r);
    float* p_cs    = symaddr(g_cs);
    float* p_corr  = symaddr(g_corr);
    float* p_corrp = symaddr(g_corrp);
    float* p_y     = symaddr(g_y);
    float* p_ycat  = symaddr(g_ycat);
    float* p_col2  = symaddr(g_col2);
    float* p_col3  = symaddr(g_col3);
    float* p_Wcat  = symaddr(g_Wcat);
    float* p_bcat  = symaddr(g_bcat);
    float* p_W4t   = symaddr(g_W4t);
    float* p_W2bt  = symaddr(g_W2bt);
    float* p_W3bt  = symaddr(g_W3bt);

    cudaFuncSetAttribute(gemm_tc, cudaFuncAttributeMaxDynamicSharedMemorySize,
                         GEMM_SMEM);

    const int T = 256;
    // 1: weight transposes + bias concat
    transpose_all_kernel<<<(819712 + MCAT + T-1)/T, T>>>(
        W1, W2a, W3a, W4, W2b, W3b, b1, b2a, b3a,
        p_Wcat, p_bcat, p_W4t, p_W2bt, p_W3bt);
    // 2-3
    resize2_kernel<<<(2*BB*CC*QQ + T-1)/T, T>>>(f1, f2);
    maskpool_kernel<<<(NTOT + T-1)/T, T>>>(mask);

    // 4: cost volume
    {
        dim3 g(7, 7, BB);
        gemm_tc<<<g, 256, GEMM_SMEM>>>(p_f1r, (size_t)CC*QQ, QQ,
                                       p_f2r, (size_t)CC*QQ, QQ,
                                       p_corr, (size_t)QQ, NTOT,
                                       nullptr, nullptr, PP, QQ, CC);
    }
    // 5
    colnorm_kernel<<<(NTOT + T-1)/T, T>>>();

    // 6: merged 1x1 GEMM (y1 + y2a + y3a, M=352)  <-- ncu captures this
    {
        dim3 g(196, 3, 1);
        gemm_tc<<<g, 256, GEMM_SMEM>>>(p_Wcat, 0, MCAT, p_corr, 0, NTOT,
                                       p_ycat, 0, NTOT, p_bcat, p_cs,
                                       MCAT, NTOT, 784);
    }
    // 7-8: pooled branch
    mp3_kernel<<<(PP*NT4 + T-1)/T, T>>>();
    {
        dim3 g1(196, 1, 1);
        gemm_tc<<<g1, 256, GEMM_SMEM>>>(p_W4t, 0, 64, p_corrp, 0, NTOT,
                                        p_y + (size_t)448*NTOT, 0, NTOT,
                                        b4, nullptr, 64, NTOT, 784);
    }
    // 9-10: 3x3 conv 192->256
    im2col3_kernel<<<(1728*NT4 + T-1)/T, T>>>();
    {
        dim3 g(196, 2, 1);
        gemm_tc<<<g, 256, GEMM_SMEM>>>(p_W2bt, 0, 256, p_col2, 0, NTOT,
                                       p_y + (size_t)128*NTOT, 0, NTOT,
                                       b2b, nullptr, 256, NTOT, 1728);
    }
    // 11-12: 5x5 conv 32->64
    im2col5_kernel<<<(800*NT4 + T-1)/T, T>>>();
    {
        dim3 g(196, 1, 1);
        gemm_tc<<<g, 256, GEMM_SMEM>>>(p_W3bt, 0, 64, p_col3, 0, NTOT,
                                       p_y + (size_t)384*NTOT, 0, NTOT,
                                       b3b, nullptr, 64, NTOT, 800);
    }
    // 13-14: BatchNorm
    bnstats_kernel<<<512, 256>>>();
    bnapply_kernel<<<(BB*512*(QQ/4) + T-1)/T, T>>>(gamma, beta, out);
}